// round 1
// baseline (speedup 1.0000x reference)
#include <cuda_runtime.h>

typedef unsigned long long u64;

#define NN 50000
#define IC 256
#define HDIM 1024
#define NH 8
#define DD 128

// Scratch (device globals: allocation-free per harness rules)
__device__ float g_Q[NN * HDIM];
__device__ float g_K[NN * HDIM];
__device__ float g_V[NN * HDIM];
__device__ float g_kvs[NH * DD * DD];   // raw K^T V per head
__device__ float g_ksum[HDIM];          // column sums of K
__device__ float g_ssq[2];              // sum(Q^2), sum(K^2)

// ---------- packed f32x2 helpers (Blackwell full-rate fp32 path) ----------
__device__ __forceinline__ u64 pack2(float x, float y) {
    u64 r; asm("mov.b64 %0, {%1, %2};" : "=l"(r) : "f"(x), "f"(y)); return r;
}
__device__ __forceinline__ void unpack2(u64 v, float &x, float &y) {
    asm("mov.b64 {%0, %1}, %2;" : "=f"(x), "=f"(y) : "l"(v));
}
__device__ __forceinline__ u64 ffma2(u64 a, u64 b, u64 c) {
    u64 d; asm("fma.rn.f32x2 %0, %1, %2, %3;" : "=l"(d) : "l"(a), "l"(b), "l"(c));
    return d;
}

// ---------- kernel 0: zero accumulators (must run every replay) ----------
__global__ void zero_kernel() {
    int i = blockIdx.x * 256 + threadIdx.x;
    if (i < NH * DD * DD) g_kvs[i] = 0.0f;
    if (i < HDIM) g_ksum[i] = 0.0f;
    if (i < 2) g_ssq[i] = 0.0f;
}

// ---------- kernel 1: C[N,1024] = A[N,256] @ W[256,1024] + bias ----------
// 128x128 tile, BK=32, 256 threads, 8x8 microtile, f32x2 accumulators.
__global__ __launch_bounds__(256, 2)
void gemm_proj(const float* __restrict__ A, const float* __restrict__ W,
               const float* __restrict__ bias, int which) {
    __shared__ float As[32][128];  // [k][m] (transposed)
    __shared__ float Ws[32][128];  // [k][n]

    float* C = (which == 0) ? g_Q : (which == 1) ? g_K : g_V;

    const int tid = threadIdx.x;
    const int tx = tid & 15;      // col group
    const int ty = tid >> 4;      // row group
    const int m0 = blockIdx.y * 128;
    const int n0 = blockIdx.x * 128;

    u64 acc[8][4];
#pragma unroll
    for (int i = 0; i < 8; i++)
#pragma unroll
        for (int j = 0; j < 4; j++) acc[i][j] = 0ull;

    for (int kt = 0; kt < IC; kt += 32) {
        // load A tile (transpose into As[k][m])
#pragma unroll
        for (int i = 0; i < 4; i++) {
            int idx = tid + i * 256;        // 0..1023
            int row = idx >> 3;             // 0..127
            int kq  = idx & 7;              // float4 group along k
            float4 v = make_float4(0.f, 0.f, 0.f, 0.f);
            int gr = m0 + row;
            if (gr < NN) v = *(const float4*)(A + (size_t)gr * IC + kt + kq * 4);
            As[kq * 4 + 0][row] = v.x;
            As[kq * 4 + 1][row] = v.y;
            As[kq * 4 + 2][row] = v.z;
            As[kq * 4 + 3][row] = v.w;
        }
        // load W tile
#pragma unroll
        for (int i = 0; i < 4; i++) {
            int idx = tid + i * 256;
            int kr = idx >> 5;              // 0..31
            int nq = idx & 31;
            *(float4*)(&Ws[kr][nq * 4]) =
                *(const float4*)(W + (size_t)(kt + kr) * HDIM + n0 + nq * 4);
        }
        __syncthreads();

#pragma unroll 8
        for (int kk = 0; kk < 32; kk++) {
            float4 a0 = *(const float4*)(&As[kk][ty * 8]);
            float4 a1 = *(const float4*)(&As[kk][ty * 8 + 4]);
            ulonglong2 bb0 = *(const ulonglong2*)(&Ws[kk][tx * 8]);
            ulonglong2 bb1 = *(const ulonglong2*)(&Ws[kk][tx * 8 + 4]);
            u64 b[4] = {bb0.x, bb0.y, bb1.x, bb1.y};
            float av[8] = {a0.x, a0.y, a0.z, a0.w, a1.x, a1.y, a1.z, a1.w};
#pragma unroll
            for (int i = 0; i < 8; i++) {
                u64 ap = pack2(av[i], av[i]);
#pragma unroll
                for (int jp = 0; jp < 4; jp++) acc[i][jp] = ffma2(ap, b[jp], acc[i][jp]);
            }
        }
        __syncthreads();
    }

    // epilogue: + bias, store
#pragma unroll
    for (int i = 0; i < 8; i++) {
        int gr = m0 + ty * 8 + i;
        if (gr < NN) {
#pragma unroll
            for (int jp = 0; jp < 4; jp++) {
                float lo, hi; unpack2(acc[i][jp], lo, hi);
                int c = n0 + tx * 8 + jp * 2;
                float2 o; o.x = lo + bias[c]; o.y = hi + bias[c + 1];
                *(float2*)(&C[(size_t)gr * HDIM + c]) = o;
            }
        }
    }
}

// ---------- kernel 2: stats: ssq(Q), ssq(K), column sums of K ----------
__global__ __launch_bounds__(256)
void stats_kernel() {
    __shared__ float red[256];
    const int t = threadIdx.x;
    float ks[4] = {0.f, 0.f, 0.f, 0.f};
    float sq = 0.f, sk = 0.f;
    for (int r = blockIdx.x; r < NN; r += gridDim.x) {
        size_t base = (size_t)r * HDIM;
#pragma unroll
        for (int j = 0; j < 4; j++) {
            float kv = g_K[base + t + j * 256];
            ks[j] += kv;
            sk += kv * kv;
            float qv = g_Q[base + t + j * 256];
            sq += qv * qv;
        }
    }
#pragma unroll
    for (int j = 0; j < 4; j++) atomicAdd(&g_ksum[t + j * 256], ks[j]);

    red[t] = sq; __syncthreads();
    for (int s2 = 128; s2 > 0; s2 >>= 1) {
        if (t < s2) red[t] += red[t + s2];
        __syncthreads();
    }
    if (t == 0) atomicAdd(&g_ssq[0], red[0]);
    __syncthreads();
    red[t] = sk; __syncthreads();
    for (int s2 = 128; s2 > 0; s2 >>= 1) {
        if (t < s2) red[t] += red[t + s2];
        __syncthreads();
    }
    if (t == 0) atomicAdd(&g_ssq[1], red[0]);
}

// ---------- kernel 3: split-K  kvs[h] += K_h^T @ V_h over a row chunk ----------
#define RCHUNK 512
__global__ __launch_bounds__(256, 2)
void ktv_kernel() {
    __shared__ float Ks[32][128];
    __shared__ float Vs[32][128];
    const int tid = threadIdx.x;
    const int tx = tid & 15;
    const int ty = tid >> 4;
    const int h = blockIdx.y;
    const int r0 = blockIdx.x * RCHUNK;
    const int rend = min(r0 + RCHUNK, NN);

    u64 acc[8][4];
#pragma unroll
    for (int i = 0; i < 8; i++)
#pragma unroll
        for (int j = 0; j < 4; j++) acc[i][j] = 0ull;

    for (int rb = r0; rb < rend; rb += 32) {
#pragma unroll
        for (int i = 0; i < 4; i++) {
            int idx = tid + i * 256;        // 0..1023
            int r = idx >> 5;               // 0..31
            int cq = idx & 31;
            int gr = rb + r;
            float4 kv = make_float4(0.f, 0.f, 0.f, 0.f);
            float4 vv = make_float4(0.f, 0.f, 0.f, 0.f);
            if (gr < NN) {
                size_t base = (size_t)gr * HDIM + h * DD + cq * 4;
                kv = *(const float4*)(g_K + base);
                vv = *(const float4*)(g_V + base);
            }
            *(float4*)(&Ks[r][cq * 4]) = kv;
            *(float4*)(&Vs[r][cq * 4]) = vv;
        }
        __syncthreads();

#pragma unroll 8
        for (int kk = 0; kk < 32; kk++) {
            float4 a0 = *(const float4*)(&Ks[kk][ty * 8]);
            float4 a1 = *(const float4*)(&Ks[kk][ty * 8 + 4]);
            ulonglong2 bb0 = *(const ulonglong2*)(&Vs[kk][tx * 8]);
            ulonglong2 bb1 = *(const ulonglong2*)(&Vs[kk][tx * 8 + 4]);
            u64 b[4] = {bb0.x, bb0.y, bb1.x, bb1.y};
            float av[8] = {a0.x, a0.y, a0.z, a0.w, a1.x, a1.y, a1.z, a1.w};
#pragma unroll
            for (int i = 0; i < 8; i++) {
                u64 ap = pack2(av[i], av[i]);
#pragma unroll
                for (int jp = 0; jp < 4; jp++) acc[i][jp] = ffma2(ap, b[jp], acc[i][jp]);
            }
        }
        __syncthreads();
    }

    float* dst = g_kvs + h * DD * DD;
#pragma unroll
    for (int i = 0; i < 8; i++) {
        int m = ty * 8 + i;
#pragma unroll
        for (int jp = 0; jp < 4; jp++) {
            float lo, hi; unpack2(acc[i][jp], lo, hi);
            int d = tx * 8 + jp * 2;
            atomicAdd(&dst[m * DD + d], lo);
            atomicAdd(&dst[m * DD + d + 1], hi);
        }
    }
}

// ---------- kernel 4: final combine ----------
// out[n,d] = (1/8) sum_h ( (Q_nh . kvs_h[:,d]) * s + NN * V[n,h,d] )
//                         / ( (Q_nh . ksum_h) * s + NN )
#define FINAL_SMEM ((16384 + 16384 + 128 + 128) * 4)
__global__ __launch_bounds__(256, 1)
void final_kernel(float* __restrict__ out) {
    extern __shared__ float sm[];
    float* kvsS  = sm;                 // [m][d] 128x128
    float* qS    = sm + 16384;         // [m][row] 128x128 (transposed Q tile)
    float* ksumS = sm + 32768;         // 128
    float* rnorm = sm + 32896;         // 128

    const int tid = threadIdx.x;
    const int tx = tid & 15;
    const int ty = tid >> 4;
    const int n0 = blockIdx.x * 128;

    const float s = rsqrtf(g_ssq[0]) * rsqrtf(g_ssq[1]);

    float outacc[8][8];
#pragma unroll
    for (int i = 0; i < 8; i++)
#pragma unroll
        for (int j = 0; j < 8; j++) outacc[i][j] = 0.f;

    for (int h = 0; h < NH; h++) {
        __syncthreads();   // previous iteration's smem readers done
        // load kvs_h (row-major matches)
#pragma unroll
        for (int i = 0; i < 16; i++) {
            int idx = tid + i * 256;
            *(float4*)(kvsS + idx * 4) = *(const float4*)(g_kvs + h * 16384 + idx * 4);
        }
        // load Q tile transposed: qS[m][row]
#pragma unroll
        for (int i = 0; i < 16; i++) {
            int idx = tid + i * 256;    // 0..4095
            int row = idx >> 5;         // 0..127
            int mq = idx & 31;
            float4 v = make_float4(0.f, 0.f, 0.f, 0.f);
            int gr = n0 + row;
            if (gr < NN) v = *(const float4*)(g_Q + (size_t)gr * HDIM + h * DD + mq * 4);
            qS[(mq * 4 + 0) * 128 + row] = v.x;
            qS[(mq * 4 + 1) * 128 + row] = v.y;
            qS[(mq * 4 + 2) * 128 + row] = v.z;
            qS[(mq * 4 + 3) * 128 + row] = v.w;
        }
        if (tid < 32)
            *(float4*)(ksumS + tid * 4) = *(const float4*)(g_ksum + h * DD + tid * 4);
        __syncthreads();

        // per-row normalizer reciprocal
        if (tid < 128) {
            float dot = 0.f;
#pragma unroll 8
            for (int m = 0; m < 128; m++) dot += qS[m * 128 + tid] * ksumS[m];
            rnorm[tid] = 1.0f / (dot * s + (float)NN);
        }
        __syncthreads();

        // 128x128x128 GEMM: num_raw[row,d] = sum_m q[row,m] * kvs[m,d]
        u64 acc[8][4];
#pragma unroll
        for (int i = 0; i < 8; i++)
#pragma unroll
            for (int j = 0; j < 4; j++) acc[i][j] = 0ull;

#pragma unroll 8
        for (int m = 0; m < 128; m++) {
            float4 a0 = *(const float4*)(qS + m * 128 + ty * 8);
            float4 a1 = *(const float4*)(qS + m * 128 + ty * 8 + 4);
            ulonglong2 bb0 = *(const ulonglong2*)(kvsS + m * 128 + tx * 8);
            ulonglong2 bb1 = *(const ulonglong2*)(kvsS + m * 128 + tx * 8 + 4);
            u64 b[4] = {bb0.x, bb0.y, bb1.x, bb1.y};
            float av[8] = {a0.x, a0.y, a0.z, a0.w, a1.x, a1.y, a1.z, a1.w};
#pragma unroll
            for (int i = 0; i < 8; i++) {
                u64 ap = pack2(av[i], av[i]);
#pragma unroll
                for (int jp = 0; jp < 4; jp++) acc[i][jp] = ffma2(ap, b[jp], acc[i][jp]);
            }
        }

        // combine: (num*s + NN*V) * rnorm
#pragma unroll
        for (int i = 0; i < 8; i++) {
            int row = ty * 8 + i;
            int gr = n0 + row;
            float rn = rnorm[row];
            float4 v0 = make_float4(0.f, 0.f, 0.f, 0.f);
            float4 v1 = make_float4(0.f, 0.f, 0.f, 0.f);
            if (gr < NN) {
                size_t vb = (size_t)gr * HDIM + h * DD + tx * 8;
                v0 = *(const float4*)(g_V + vb);
                v1 = *(const float4*)(g_V + vb + 4);
            }
            float vv[8] = {v0.x, v0.y, v0.z, v0.w, v1.x, v1.y, v1.z, v1.w};
#pragma unroll
            for (int jp = 0; jp < 4; jp++) {
                float lo, hi; unpack2(acc[i][jp], lo, hi);
                outacc[i][jp * 2 + 0] += (lo * s + (float)NN * vv[jp * 2 + 0]) * rn;
                outacc[i][jp * 2 + 1] += (hi * s + (float)NN * vv[jp * 2 + 1]) * rn;
            }
        }
    }

    // write: mean over heads
#pragma unroll
    for (int i = 0; i < 8; i++) {
        int gr = n0 + ty * 8 + i;
        if (gr < NN) {
            float4 o0, o1;
            o0.x = outacc[i][0] * 0.125f; o0.y = outacc[i][1] * 0.125f;
            o0.z = outacc[i][2] * 0.125f; o0.w = outacc[i][3] * 0.125f;
            o1.x = outacc[i][4] * 0.125f; o1.y = outacc[i][5] * 0.125f;
            o1.z = outacc[i][6] * 0.125f; o1.w = outacc[i][7] * 0.125f;
            *(float4*)(&out[(size_t)gr * DD + tx * 8]) = o0;
            *(float4*)(&out[(size_t)gr * DD + tx * 8 + 4]) = o1;
        }
    }
}

// ---------- launcher ----------
extern "C" void kernel_launch(void* const* d_in, const int* in_sizes, int n_in,
                              void* d_out, int out_size) {
    const float* xq = (const float*)d_in[0];   // query_input [N,256]
    const float* xs = (const float*)d_in[1];   // source_input [N,256]
    const float* Wq = (const float*)d_in[2];
    const float* bq = (const float*)d_in[3];
    const float* Wk = (const float*)d_in[4];
    const float* bk = (const float*)d_in[5];
    const float* Wv = (const float*)d_in[6];
    const float* bv = (const float*)d_in[7];
    float* out = (float*)d_out;

    cudaFuncSetAttribute(final_kernel, cudaFuncAttributeMaxDynamicSharedMemorySize,
                         FINAL_SMEM);

    zero_kernel<<<512, 256>>>();

    dim3 gg(8, (NN + 127) / 128);   // (1024/128, ceil(N/128))
    gemm_proj<<<gg, 256>>>(xq, Wq, bq, 0);   // Q
    gemm_proj<<<gg, 256>>>(xs, Wk, bk, 1);   // K
    gemm_proj<<<gg, 256>>>(xs, Wv, bv, 2);   // V

    stats_kernel<<<512, 256>>>();

    dim3 gk((NN + RCHUNK - 1) / RCHUNK, NH);
    ktv_kernel<<<gk, 256>>>();

    final_kernel<<<(NN + 127) / 128, 256, FINAL_SMEM>>>(out);
}

// round 4
// speedup vs baseline: 1.7434x; 1.7434x over previous
#include <cuda_runtime.h>
#include <cstdint>

typedef unsigned long long u64;

#define NN 50000
#define IC 256
#define HDIM 1024
#define NH 8
#define DD 128

// Scratch (device globals: allocation-free per harness rules)
__device__ float g_Q[NN * HDIM];
__device__ float g_K[NN * HDIM];
__device__ float g_V[NN * HDIM];
__device__ float g_Wp[3 * HDIM * IC];   // fragment-packed tf32 weights
__device__ float g_kvs[NH * DD * DD];
__device__ float g_ksum[HDIM];
__device__ float g_ssq[2];

// ---------- packed f32x2 helpers ----------
__device__ __forceinline__ u64 pack2(float x, float y) {
    u64 r; asm("mov.b64 %0, {%1, %2};" : "=l"(r) : "f"(x), "f"(y)); return r;
}
__device__ __forceinline__ void unpack2(u64 v, float &x, float &y) {
    asm("mov.b64 {%0, %1}, %2;" : "=f"(x), "=f"(y) : "l"(v));
}
__device__ __forceinline__ u64 ffma2(u64 a, u64 b, u64 c) {
    u64 d; asm("fma.rn.f32x2 %0, %1, %2, %3;" : "=l"(d) : "l"(a), "l"(b), "l"(c));
    return d;
}
__device__ __forceinline__ float to_tf32(float x) {
    float r; asm("cvt.rna.tf32.f32 %0, %1;" : "=f"(r) : "f"(x)); return r;
}
__device__ __forceinline__ uint32_t smem_to_u32(const void* p) {
    uint32_t a;
    asm("{ .reg .u64 t; cvta.to.shared.u64 t, %1; cvt.u32.u64 %0, t; }" : "=r"(a) : "l"(p));
    return a;
}
__device__ __forceinline__ void cp_async16(uint32_t dst, const void* src) {
    asm volatile("cp.async.cg.shared.global [%0], [%1], 16;" :: "r"(dst), "l"(src));
}

// mma.sync m16n8k8 tf32 (arch-agnostic PTX, maps to HMMA on sm_103)
// Fragment mapping (verified vs CUTLASS SM80_16x8x8_F32TF32TF32F32_TN):
//  A: a0=(r,c) a1=(r+8,c) a2=(r,c+4) a3=(r+8,c+4), r=lane/4, c=lane%4
//  B: b0=(k=lane%4, n=lane/4) b1=(k+4, n)
//  D: d0=(r, 2c) d1=(r, 2c+1) d2=(r+8, 2c) d3=(r+8, 2c+1)
__device__ __forceinline__ void mma_tf32(float* d, const uint32_t* a, const uint32_t* b) {
    asm volatile(
        "mma.sync.aligned.m16n8k8.row.col.f32.tf32.tf32.f32 "
        "{%0,%1,%2,%3}, {%4,%5,%6,%7}, {%8,%9}, {%0,%1,%2,%3};"
        : "+f"(d[0]), "+f"(d[1]), "+f"(d[2]), "+f"(d[3])
        : "r"(a[0]), "r"(a[1]), "r"(a[2]), "r"(a[3]), "r"(b[0]), "r"(b[1]));
}

// ---------- kernel 0: zero accumulators ----------
__global__ void zero_kernel() {
    int i = blockIdx.x * 256 + threadIdx.x;
    if (i < NH * DD * DD) g_kvs[i] = 0.0f;
    if (i < HDIM) g_ksum[i] = 0.0f;
    if (i < 2) g_ssq[i] = 0.0f;
}

// ---------- pack W into per-lane fragment images ----------
// For n-block (256 cols) nblk, chunk c (32 k), the smem image holds
// idx = ((nt*4 + ks)*32 + lane)*2 + s  at float granularity, where
// nt=(n%256)/8, ks=(k/8)%4, lane=(n%8)*4 + k%4, s=(k/4)%2.
__global__ void pack_W(const float* __restrict__ Wq,
                       const float* __restrict__ Wk,
                       const float* __restrict__ Wv) {
    int which = blockIdx.y;
    const float* W = (which == 0) ? Wq : (which == 1) ? Wk : Wv;
    int e = blockIdx.x * 256 + threadIdx.x;       // 0..262143 = k*1024+n
    int k = e >> 10, n = e & 1023;
    float v = to_tf32(W[e]);
    int nblk = n >> 8, nn = n & 255;
    int nt = nn >> 3;
    int c = k >> 5, ks = (k >> 3) & 3, s = (k >> 2) & 1;
    int l = ((nn & 7) << 2) | (k & 3);
    g_Wp[(size_t)which * 262144 + (size_t)nblk * 65536 + c * 8192 +
         ((nt * 4 + ks) * 32 + l) * 2 + s] = v;
}

// ---------- projection GEMM via mma.sync tf32 ----------
// C[N,1024] = A[N,256] @ W + bias. Block tile 128x256, warps 2x4, warp 64x64.
// A resident in smem (stride 260 -> conflict-free frag LDS), B double-buffered
// cp.async from pre-packed g_Wp.
#define AS_STRIDE 260
#define GEMM_SMEM ((128 * AS_STRIDE + 2 * 8192) * 4)

__global__ __launch_bounds__(256, 1) void gemm_mma(
    const float* __restrict__ A, const float* __restrict__ Wp,
    const float* __restrict__ bias, float* __restrict__ C) {
    extern __shared__ float sm[];
    float* As = sm;                         // 128 x 260
    float* Bs = sm + 128 * AS_STRIDE;       // 2 x 8192

    const int tid = threadIdx.x;
    const int lane = tid & 31;
    const int wid = tid >> 5;
    const int warpM = wid >> 2;             // 0..1
    const int warpN = wid & 3;              // 0..3
    const int m0 = blockIdx.x * 128;
    const float* WpB = Wp + (size_t)blockIdx.y * 65536;

    // load A block tile (coalesced LDG.128 -> clean STS.128), tf32-rounded
#pragma unroll 4
    for (int i = 0; i < 32; i++) {
        int idx = tid + i * 256;
        int r = idx >> 6, q = idx & 63;
        int gr = m0 + r;
        float4 v = make_float4(0.f, 0.f, 0.f, 0.f);
        if (gr < NN) v = *(const float4*)(A + (size_t)gr * IC + q * 4);
        v.x = to_tf32(v.x); v.y = to_tf32(v.y);
        v.z = to_tf32(v.z); v.w = to_tf32(v.w);
        *(float4*)(As + r * AS_STRIDE + q * 4) = v;
    }

    // prologue: chunk 0
    {
        uint32_t dst = smem_to_u32(Bs);
#pragma unroll
        for (int i = 0; i < 8; i++) {
            int o = (tid + i * 256) * 16;
            cp_async16(dst + o, (const char*)WpB + o);
        }
        asm volatile("cp.async.commit_group;");
    }

    float acc[4][8][4];
#pragma unroll
    for (int mt = 0; mt < 4; mt++)
#pragma unroll
        for (int j = 0; j < 8; j++)
#pragma unroll
            for (int v = 0; v < 4; v++) acc[mt][j][v] = 0.f;

    const int aRow = warpM * 64 + (lane >> 2);
    const int aCol = lane & 3;

    for (int c = 0; c < 8; c++) {
        if (c < 7) {
            uint32_t dst = smem_to_u32(Bs + ((c + 1) & 1) * 8192);
            const char* src = (const char*)WpB + (c + 1) * 32768;
#pragma unroll
            for (int i = 0; i < 8; i++) {
                int o = (tid + i * 256) * 16;
                cp_async16(dst + o, src + o);
            }
            asm volatile("cp.async.commit_group;");
            asm volatile("cp.async.wait_group 1;");
        } else {
            asm volatile("cp.async.wait_group 0;");
        }
        __syncthreads();

        const float* Bc = Bs + (c & 1) * 8192;
#pragma unroll
        for (int ks = 0; ks < 4; ks++) {
            int k0 = c * 32 + ks * 8;
            uint32_t a[4][4];
#pragma unroll
            for (int mt = 0; mt < 4; mt++) {
                const float* p = As + (aRow + mt * 16) * AS_STRIDE + k0 + aCol;
                a[mt][0] = __float_as_uint(p[0]);
                a[mt][1] = __float_as_uint(p[8 * AS_STRIDE]);
                a[mt][2] = __float_as_uint(p[4]);
                a[mt][3] = __float_as_uint(p[8 * AS_STRIDE + 4]);
            }
            uint32_t b[8][2];
#pragma unroll
            for (int j = 0; j < 8; j++) {
                int nt = warpN * 8 + j;
                float2 bb = *(const float2*)(Bc + ((nt * 4 + ks) * 32 + lane) * 2);
                b[j][0] = __float_as_uint(bb.x);
                b[j][1] = __float_as_uint(bb.y);
            }
#pragma unroll
            for (int mt = 0; mt < 4; mt++)
#pragma unroll
                for (int j = 0; j < 8; j++)
                    mma_tf32(acc[mt][j], a[mt], b[j]);
        }
        __syncthreads();
    }

    // epilogue: +bias, store float2 per fragment pair
    const int n0 = blockIdx.y * 256 + warpN * 64;
#pragma unroll
    for (int j = 0; j < 8; j++) {
        int col = n0 + j * 8 + 2 * (lane & 3);
        float2 bv = *(const float2*)(bias + col);
#pragma unroll
        for (int mt = 0; mt < 4; mt++) {
            int row = m0 + warpM * 64 + mt * 16 + (lane >> 2);
            if (row < NN) {
                float2 o;
                o.x = acc[mt][j][0] + bv.x;
                o.y = acc[mt][j][1] + bv.y;
                *(float2*)(C + (size_t)row * HDIM + col) = o;
            }
            if (row + 8 < NN) {
                float2 o;
                o.x = acc[mt][j][2] + bv.x;
                o.y = acc[mt][j][3] + bv.y;
                *(float2*)(C + (size_t)(row + 8) * HDIM + col) = o;
            }
        }
    }
}

// ---------- kernel 2: stats ----------
__global__ __launch_bounds__(256)
void stats_kernel() {
    __shared__ float red[256];
    const int t = threadIdx.x;
    float ks[4] = {0.f, 0.f, 0.f, 0.f};
    float sq = 0.f, sk = 0.f;
    for (int r = blockIdx.x; r < NN; r += gridDim.x) {
        size_t base = (size_t)r * HDIM;
#pragma unroll
        for (int j = 0; j < 4; j++) {
            float kv = g_K[base + t + j * 256];
            ks[j] += kv;
            sk += kv * kv;
            float qv = g_Q[base + t + j * 256];
            sq += qv * qv;
        }
    }
#pragma unroll
    for (int j = 0; j < 4; j++) atomicAdd(&g_ksum[t + j * 256], ks[j]);

    red[t] = sq; __syncthreads();
    for (int s2 = 128; s2 > 0; s2 >>= 1) {
        if (t < s2) red[t] += red[t + s2];
        __syncthreads();
    }
    if (t == 0) atomicAdd(&g_ssq[0], red[0]);
    __syncthreads();
    red[t] = sk; __syncthreads();
    for (int s2 = 128; s2 > 0; s2 >>= 1) {
        if (t < s2) red[t] += red[t + s2];
        __syncthreads();
    }
    if (t == 0) atomicAdd(&g_ssq[1], red[0]);
}

// ---------- kernel 3: split-K kvs[h] += K_h^T @ V_h ----------
#define RCHUNK 512
__global__ __launch_bounds__(256, 2)
void ktv_kernel() {
    __shared__ float Ks[32][128];
    __shared__ float Vs[32][128];
    const int tid = threadIdx.x;
    const int tx = tid & 15;
    const int ty = tid >> 4;
    const int h = blockIdx.y;
    const int r0 = blockIdx.x * RCHUNK;
    const int rend = min(r0 + RCHUNK, NN);

    u64 acc[8][4];
#pragma unroll
    for (int i = 0; i < 8; i++)
#pragma unroll
        for (int j = 0; j < 4; j++) acc[i][j] = 0ull;

    for (int rb = r0; rb < rend; rb += 32) {
#pragma unroll
        for (int i = 0; i < 4; i++) {
            int idx = tid + i * 256;
            int r = idx >> 5;
            int cq = idx & 31;
            int gr = rb + r;
            float4 kv = make_float4(0.f, 0.f, 0.f, 0.f);
            float4 vv = make_float4(0.f, 0.f, 0.f, 0.f);
            if (gr < NN) {
                size_t base = (size_t)gr * HDIM + h * DD + cq * 4;
                kv = *(const float4*)(g_K + base);
                vv = *(const float4*)(g_V + base);
            }
            *(float4*)(&Ks[r][cq * 4]) = kv;
            *(float4*)(&Vs[r][cq * 4]) = vv;
        }
        __syncthreads();

#pragma unroll 8
        for (int kk = 0; kk < 32; kk++) {
            float4 a0 = *(const float4*)(&Ks[kk][ty * 8]);
            float4 a1 = *(const float4*)(&Ks[kk][ty * 8 + 4]);
            ulonglong2 bb0 = *(const ulonglong2*)(&Vs[kk][tx * 8]);
            ulonglong2 bb1 = *(const ulonglong2*)(&Vs[kk][tx * 8 + 4]);
            u64 b[4] = {bb0.x, bb0.y, bb1.x, bb1.y};
            float av[8] = {a0.x, a0.y, a0.z, a0.w, a1.x, a1.y, a1.z, a1.w};
#pragma unroll
            for (int i = 0; i < 8; i++) {
                u64 ap = pack2(av[i], av[i]);
#pragma unroll
                for (int jp = 0; jp < 4; jp++) acc[i][jp] = ffma2(ap, b[jp], acc[i][jp]);
            }
        }
        __syncthreads();
    }

    float* dst = g_kvs + h * DD * DD;
#pragma unroll
    for (int i = 0; i < 8; i++) {
        int m = ty * 8 + i;
#pragma unroll
        for (int jp = 0; jp < 4; jp++) {
            float lo, hi; unpack2(acc[i][jp], lo, hi);
            int d = tx * 8 + jp * 2;
            atomicAdd(&dst[m * DD + d], lo);
            atomicAdd(&dst[m * DD + d + 1], hi);
        }
    }
}

// ---------- kernel 4: final combine ----------
#define FINAL_SMEM ((16384 + 16384 + 128 + 128) * 4)
__global__ __launch_bounds__(256, 1)
void final_kernel(float* __restrict__ out) {
    extern __shared__ float sm[];
    float* kvsS  = sm;
    float* qS    = sm + 16384;
    float* ksumS = sm + 32768;
    float* rnorm = sm + 32896;

    const int tid = threadIdx.x;
    const int tx = tid & 15;
    const int ty = tid >> 4;
    const int n0 = blockIdx.x * 128;

    const float s = rsqrtf(g_ssq[0]) * rsqrtf(g_ssq[1]);

    float outacc[8][8];
#pragma unroll
    for (int i = 0; i < 8; i++)
#pragma unroll
        for (int j = 0; j < 8; j++) outacc[i][j] = 0.f;

    for (int h = 0; h < NH; h++) {
        __syncthreads();
#pragma unroll
        for (int i = 0; i < 16; i++) {
            int idx = tid + i * 256;
            *(float4*)(kvsS + idx * 4) = *(const float4*)(g_kvs + h * 16384 + idx * 4);
        }
#pragma unroll
        for (int i = 0; i < 16; i++) {
            int idx = tid + i * 256;
            int row = idx >> 5;
            int mq = idx & 31;
            float4 v = make_float4(0.f, 0.f, 0.f, 0.f);
            int gr = n0 + row;
            if (gr < NN) v = *(const float4*)(g_Q + (size_t)gr * HDIM + h * DD + mq * 4);
            qS[(mq * 4 + 0) * 128 + row] = v.x;
            qS[(mq * 4 + 1) * 128 + row] = v.y;
            qS[(mq * 4 + 2) * 128 + row] = v.z;
            qS[(mq * 4 + 3) * 128 + row] = v.w;
        }
        if (tid < 32)
            *(float4*)(ksumS + tid * 4) = *(const float4*)(g_ksum + h * DD + tid * 4);
        __syncthreads();

        if (tid < 128) {
            float dot = 0.f;
#pragma unroll 8
            for (int m = 0; m < 128; m++) dot += qS[m * 128 + tid] * ksumS[m];
            rnorm[tid] = 1.0f / (dot * s + (float)NN);
        }
        __syncthreads();

        u64 acc[8][4];
#pragma unroll
        for (int i = 0; i < 8; i++)
#pragma unroll
            for (int j = 0; j < 4; j++) acc[i][j] = 0ull;

#pragma unroll 8
        for (int m = 0; m < 128; m++) {
            float4 a0 = *(const float4*)(qS + m * 128 + ty * 8);
            float4 a1 = *(const float4*)(qS + m * 128 + ty * 8 + 4);
            ulonglong2 bb0 = *(const ulonglong2*)(kvsS + m * 128 + tx * 8);
            ulonglong2 bb1 = *(const ulonglong2*)(kvsS + m * 128 + tx * 8 + 4);
            u64 b[4] = {bb0.x, bb0.y, bb1.x, bb1.y};
            float av[8] = {a0.x, a0.y, a0.z, a0.w, a1.x, a1.y, a1.z, a1.w};
#pragma unroll
            for (int i = 0; i < 8; i++) {
                u64 ap = pack2(av[i], av[i]);
#pragma unroll
                for (int jp = 0; jp < 4; jp++) acc[i][jp] = ffma2(ap, b[jp], acc[i][jp]);
            }
        }

#pragma unroll
        for (int i = 0; i < 8; i++) {
            int row = ty * 8 + i;
            int gr = n0 + row;
            float rn = rnorm[row];
            float4 v0 = make_float4(0.f, 0.f, 0.f, 0.f);
            float4 v1 = make_float4(0.f, 0.f, 0.f, 0.f);
            if (gr < NN) {
                size_t vb = (size_t)gr * HDIM + h * DD + tx * 8;
                v0 = *(const float4*)(g_V + vb);
                v1 = *(const float4*)(g_V + vb + 4);
            }
            float vv[8] = {v0.x, v0.y, v0.z, v0.w, v1.x, v1.y, v1.z, v1.w};
#pragma unroll
            for (int jp = 0; jp < 4; jp++) {
                float lo, hi; unpack2(acc[i][jp], lo, hi);
                outacc[i][jp * 2 + 0] += (lo * s + (float)NN * vv[jp * 2 + 0]) * rn;
                outacc[i][jp * 2 + 1] += (hi * s + (float)NN * vv[jp * 2 + 1]) * rn;
            }
        }
    }

#pragma unroll
    for (int i = 0; i < 8; i++) {
        int gr = n0 + ty * 8 + i;
        if (gr < NN) {
            float4 o0, o1;
            o0.x = outacc[i][0] * 0.125f; o0.y = outacc[i][1] * 0.125f;
            o0.z = outacc[i][2] * 0.125f; o0.w = outacc[i][3] * 0.125f;
            o1.x = outacc[i][4] * 0.125f; o1.y = outacc[i][5] * 0.125f;
            o1.z = outacc[i][6] * 0.125f; o1.w = outacc[i][7] * 0.125f;
            *(float4*)(&out[(size_t)gr * DD + tx * 8]) = o0;
            *(float4*)(&out[(size_t)gr * DD + tx * 8 + 4]) = o1;
        }
    }
}

// ---------- launcher ----------
extern "C" void kernel_launch(void* const* d_in, const int* in_sizes, int n_in,
                              void* d_out, int out_size) {
    const float* xq = (const float*)d_in[0];
    const float* xs = (const float*)d_in[1];
    const float* Wq = (const float*)d_in[2];
    const float* bq = (const float*)d_in[3];
    const float* Wk = (const float*)d_in[4];
    const float* bk = (const float*)d_in[5];
    const float* Wv = (const float*)d_in[6];
    const float* bv = (const float*)d_in[7];
    float* out = (float*)d_out;

    cudaFuncSetAttribute(gemm_mma, cudaFuncAttributeMaxDynamicSharedMemorySize, GEMM_SMEM);
    cudaFuncSetAttribute(final_kernel, cudaFuncAttributeMaxDynamicSharedMemorySize, FINAL_SMEM);

    zero_kernel<<<512, 256>>>();
    pack_W<<<dim3(1024, 3), 256>>>(Wq, Wk, Wv);

    float *dQ, *dK, *dV, *dWp;
    cudaGetSymbolAddress((void**)&dQ, g_Q);
    cudaGetSymbolAddress((void**)&dK, g_K);
    cudaGetSymbolAddress((void**)&dV, g_V);
    cudaGetSymbolAddress((void**)&dWp, g_Wp);

    int mblocks = (NN + 127) / 128;   // 391
    gemm_mma<<<dim3(mblocks, 4), 256, GEMM_SMEM>>>(xq, dWp + 0 * 262144, bq, dQ);
    gemm_mma<<<dim3(mblocks, 4), 256, GEMM_SMEM>>>(xs, dWp + 1 * 262144, bk, dK);
    gemm_mma<<<dim3(mblocks, 4), 256, GEMM_SMEM>>>(xs, dWp + 2 * 262144, bv, dV);

    stats_kernel<<<512, 256>>>();

    dim3 gk((NN + RCHUNK - 1) / RCHUNK, NH);
    ktv_kernel<<<gk, 256>>>();

    final_kernel<<<(NN + 127) / 128, 256, FINAL_SMEM>>>(out);
}

// round 5
// speedup vs baseline: 75.0195x; 43.0309x over previous
#include <cuda_runtime.h>
#include <cstdint>

#define NN 50000
#define IC 256
#define DD 128
#define NH 8
#define HDIM 1024

// Device scratch (allocation-free per harness rules)
__device__ float g_Wm[IC * DD];   // mean-over-heads V weight, tf32-rounded, [k][d]
__device__ float g_bm[DD];        // mean-over-heads V bias

__device__ __forceinline__ float to_tf32(float x) {
    float r; asm("cvt.rna.tf32.f32 %0, %1;" : "=f"(r) : "f"(x)); return r;
}

// mma.sync m16n8k8 tf32 (arch-agnostic PTX; HMMA on sm_103)
//  A: a0=(r,c) a1=(r+8,c) a2=(r,c+4) a3=(r+8,c+4), r=lane/4, c=lane%4
//  B: b0=(k=lane%4, n=lane/4) b1=(k+4, n)
//  D: d0=(r, 2c) d1=(r, 2c+1) d2=(r+8, 2c) d3=(r+8, 2c+1)
__device__ __forceinline__ void mma_tf32(float* d, const uint32_t* a, const uint32_t* b) {
    asm volatile(
        "mma.sync.aligned.m16n8k8.row.col.f32.tf32.tf32.f32 "
        "{%0,%1,%2,%3}, {%4,%5,%6,%7}, {%8,%9}, {%0,%1,%2,%3};"
        : "+f"(d[0]), "+f"(d[1]), "+f"(d[2]), "+f"(d[3])
        : "r"(a[0]), "r"(a[1]), "r"(a[2]), "r"(a[3]), "r"(b[0]), "r"(b[1]));
}

// ---------- prep: Wm[c][d] = tf32(mean_h Wv[c][h*128+d]); bm = mean_h bv ----------
__global__ void prep_kernel(const float* __restrict__ Wv, const float* __restrict__ bv) {
    int e = blockIdx.x * 256 + threadIdx.x;     // 0..32767
    int c = e >> 7, d = e & 127;
    float s = 0.f;
#pragma unroll
    for (int h = 0; h < NH; h++) s += Wv[(size_t)c * HDIM + h * DD + d];
    g_Wm[e] = to_tf32(s * 0.125f);
    if (e < DD) {
        float b = 0.f;
#pragma unroll
        for (int h = 0; h < NH; h++) b += bv[h * DD + e];
        g_bm[e] = b * 0.125f;
    }
}

// ---------- main GEMM: out[50000,128] = X[50000,256] @ Wm + bm ----------
// Block tile 128(M) x 128(N), 8 warps 2x4 (warp 64x32), k=256 in 8 chunks of 32.
// Wm fully smem-resident [256][136]; A chunk double-buffered [128][36], rna-rounded.
#define WS 136
#define AS 36
#define VSMEM ((IC * WS + 2 * 128 * AS) * 4)    // 176128 B

__device__ __forceinline__ void loadA(const float* __restrict__ X, int m0, int c,
                                      float4* pf, int tid) {
#pragma unroll
    for (int i = 0; i < 4; i++) {
        int idx = tid + i * 256;          // 0..1023 float4 slots
        int r = idx >> 3, q = idx & 7;
        int gr = m0 + r;
        pf[i] = (gr < NN) ? *(const float4*)(X + (size_t)gr * IC + c * 32 + q * 4)
                          : make_float4(0.f, 0.f, 0.f, 0.f);
    }
}

__global__ __launch_bounds__(256, 1) void vmean_gemm(const float* __restrict__ X,
                                                     float* __restrict__ out) {
    extern __shared__ float sm[];
    float* Ws = sm;                  // [256][136]
    float* As = sm + IC * WS;        // 2 x [128][36]

    const int tid = threadIdx.x;
    const int lane = tid & 31;
    const int wid = tid >> 5;
    const int warpM = wid >> 2;      // 0..1  (64 rows each)
    const int warpN = wid & 3;       // 0..3  (32 cols each)
    const int m0 = blockIdx.x * 128;

    // load Wm into smem [k][d] stride 136 (pre-rounded)
#pragma unroll
    for (int i = 0; i < 32; i++) {
        int idx = tid + i * 256;       // 0..8191 float4 slots
        int r = idx >> 5, q = idx & 31;
        float4 v = *(const float4*)(g_Wm + r * DD + q * 4);
        *(float4*)(Ws + r * WS + q * 4) = v;
    }

    float acc[4][4][4];
#pragma unroll
    for (int mt = 0; mt < 4; mt++)
#pragma unroll
        for (int jn = 0; jn < 4; jn++)
#pragma unroll
            for (int v = 0; v < 4; v++) acc[mt][jn][v] = 0.f;

    float4 pf[4];
    loadA(X, m0, 0, pf, tid);

    const int aRowB = warpM * 64 + (lane >> 2);
    const int aColB = lane & 3;

    for (int c = 0; c < 8; c++) {
        int buf = c & 1;
        // rna-round + stage A chunk
#pragma unroll
        for (int i = 0; i < 4; i++) {
            int idx = tid + i * 256;
            int r = idx >> 3, q = idx & 7;
            float4 v = pf[i];
            v.x = to_tf32(v.x); v.y = to_tf32(v.y);
            v.z = to_tf32(v.z); v.w = to_tf32(v.w);
            *(float4*)(As + buf * (128 * AS) + r * AS + q * 4) = v;
        }
        if (c < 7) loadA(X, m0, c + 1, pf, tid);
        __syncthreads();

        const float* Ab = As + buf * (128 * AS);
#pragma unroll
        for (int ks = 0; ks < 4; ks++) {
            int kloc = ks * 8 + aColB;
            uint32_t a[4][4];
#pragma unroll
            for (int mt = 0; mt < 4; mt++) {
                const float* p = Ab + (aRowB + mt * 16) * AS + kloc;
                a[mt][0] = __float_as_uint(p[0]);
                a[mt][1] = __float_as_uint(p[8 * AS]);
                a[mt][2] = __float_as_uint(p[4]);
                a[mt][3] = __float_as_uint(p[8 * AS + 4]);
            }
            int kg = c * 32 + ks * 8 + (lane & 3);
            uint32_t b[4][2];
#pragma unroll
            for (int jn = 0; jn < 4; jn++) {
                int d = warpN * 32 + jn * 8 + (lane >> 2);
                b[jn][0] = __float_as_uint(Ws[kg * WS + d]);
                b[jn][1] = __float_as_uint(Ws[(kg + 4) * WS + d]);
            }
#pragma unroll
            for (int mt = 0; mt < 4; mt++)
#pragma unroll
                for (int jn = 0; jn < 4; jn++)
                    mma_tf32(acc[mt][jn], a[mt], b[jn]);
        }
        __syncthreads();
    }

    // epilogue: + bm, store float2 per fragment pair
#pragma unroll
    for (int jn = 0; jn < 4; jn++) {
        int col = warpN * 32 + jn * 8 + 2 * (lane & 3);
        float2 bm2;
        bm2.x = g_bm[col];
        bm2.y = g_bm[col + 1];
#pragma unroll
        for (int mt = 0; mt < 4; mt++) {
            int row = m0 + warpM * 64 + mt * 16 + (lane >> 2);
            if (row < NN) {
                float2 o;
                o.x = acc[mt][jn][0] + bm2.x;
                o.y = acc[mt][jn][1] + bm2.y;
                *(float2*)(out + (size_t)row * DD + col) = o;
            }
            if (row + 8 < NN) {
                float2 o;
                o.x = acc[mt][jn][2] + bm2.x;
                o.y = acc[mt][jn][3] + bm2.y;
                *(float2*)(out + (size_t)(row + 8) * DD + col) = o;
            }
        }
    }
}

// ---------- launcher ----------
extern "C" void kernel_launch(void* const* d_in, const int* in_sizes, int n_in,
                              void* d_out, int out_size) {
    const float* xs = (const float*)d_in[1];   // source_input [N,256]
    const float* Wv = (const float*)d_in[6];
    const float* bv = (const float*)d_in[7];
    float* out = (float*)d_out;

    cudaFuncSetAttribute(vmean_gemm, cudaFuncAttributeMaxDynamicSharedMemorySize, VSMEM);

    prep_kernel<<<128, 256>>>(Wv, bv);
    vmean_gemm<<<(NN + 127) / 128, 256, VSMEM>>>(xs, out);
}

// round 9
// speedup vs baseline: 83.7253x; 1.1160x over previous
#include <cuda_runtime.h>
#include <cstdint>

#define NN 50000
#define IC 256
#define DD 128
#define NH 8
#define HDIM 1024

#define NTILES ((NN + 127) / 128)    // 391
#define GRID 148

// Device scratch (allocation-free per harness rules)
__device__ float g_Wm[IC * DD];   // mean-over-heads V weight, tf32-rounded, [k][d]
__device__ float g_bm[DD];        // mean-over-heads V bias

__device__ __forceinline__ float to_tf32(float x) {
    float r; asm("cvt.rna.tf32.f32 %0, %1;" : "=f"(r) : "f"(x)); return r;
}
__device__ __forceinline__ uint32_t smem_to_u32(const void* p) {
    uint32_t a;
    asm("{ .reg .u64 t; cvta.to.shared.u64 t, %1; cvt.u32.u64 %0, t; }" : "=r"(a) : "l"(p));
    return a;
}

// mma.sync m16n8k8 tf32 (arch-agnostic PTX; HMMA on sm_103)
//  A: a0=(r,c) a1=(r+8,c) a2=(r,c+4) a3=(r+8,c+4), r=lane/4, c=lane%4
//  B: b0=(k=lane%4, n=lane/4) b1=(k+4, n)
//  D: d0=(r, 2c) d1=(r, 2c+1) d2=(r+8, 2c) d3=(r+8, 2c+1)
__device__ __forceinline__ void mma_tf32(float* d, const uint32_t* a, const uint32_t* b) {
    asm volatile(
        "mma.sync.aligned.m16n8k8.row.col.f32.tf32.tf32.f32 "
        "{%0,%1,%2,%3}, {%4,%5,%6,%7}, {%8,%9}, {%0,%1,%2,%3};"
        : "+f"(d[0]), "+f"(d[1]), "+f"(d[2]), "+f"(d[3])
        : "r"(a[0]), "r"(a[1]), "r"(a[2]), "r"(a[3]), "r"(b[0]), "r"(b[1]));
}

// ---------- prep: Wm[c][d] = tf32(mean_h Wv[c][h*128+d]); bm = mean_h bv ----------
__global__ void prep_kernel(const float* __restrict__ Wv, const float* __restrict__ bv) {
    int e = blockIdx.x * 256 + threadIdx.x;     // 0..32767
    int c = e >> 7, d = e & 127;
    float s = 0.f;
#pragma unroll
    for (int h = 0; h < NH; h++) s += Wv[(size_t)c * HDIM + h * DD + d];
    g_Wm[e] = to_tf32(s * 0.125f);
    if (e < DD) {
        float b = 0.f;
#pragma unroll
        for (int h = 0; h < NH; h++) b += bv[h * DD + e];
        g_bm[e] = b * 0.125f;
    }
}

// ---------- persistent GEMM: out[50000,128] = X[50000,256] @ Wm + bm ----------
// grid=148 persistent CTAs. W resident in smem [256][136] (conflict-free B frags).
// A streamed as a ring of 32-k chunks [128][36] (conflict-free A frags), 4-stage
// cp.async pipeline crossing tile boundaries seamlessly. A fed to tf32 MMA
// unrounded (HW truncation).
#define WS 136
#define AS 36
#define RS 4
#define ASTAGE (128 * AS)
#define VSMEM ((IC * WS + RS * ASTAGE) * 4)   // 139264 + 73728 = 212992 B

__device__ __forceinline__ void issue_chunk(const float* __restrict__ X,
                                            uint32_t asBase, int bid, int g, int tid) {
    int t = bid + (g >> 3) * GRID;
    int c = g & 7;
    int m0 = t * 128;
    uint32_t dst = asBase + (g % RS) * (ASTAGE * 4);
#pragma unroll
    for (int i = 0; i < 4; i++) {
        int idx = tid + i * 256;     // 0..1023
        int r = idx >> 3, q = idx & 7;
        int gr = m0 + r;
        int grc = (gr < NN) ? gr : (NN - 1);
        const float* src = X + (size_t)grc * IC + c * 32 + q * 4;
        unsigned sz = (gr < NN) ? 16u : 0u;    // OOB rows -> smem zero-filled
        asm volatile("cp.async.cg.shared.global [%0], [%1], 16, %2;"
                     :: "r"(dst + (r * AS + q * 4) * 4), "l"(src), "r"(sz));
    }
}

__global__ __launch_bounds__(256, 1) void vmean_gemm(const float* __restrict__ X,
                                                     float* __restrict__ out) {
    extern __shared__ float sm[];
    float* Ws = sm;                  // [256][136]
    float* As = sm + IC * WS;        // RS x [128][36]

    const int tid = threadIdx.x;
    const int lane = tid & 31;
    const int wid = tid >> 5;
    const int warpM = wid >> 2;      // 0..1  (64 rows)
    const int warpN = wid & 3;       // 0..3  (32 cols)
    const int bid = blockIdx.x;

    // load Wm into smem (visible after the first __syncthreads in the loop)
#pragma unroll
    for (int i = 0; i < 32; i++) {
        int idx = tid + i * 256;       // float4 slots
        int r = idx >> 5, q = idx & 31;
        float4 v = *(const float4*)(g_Wm + r * DD + q * 4);
        *(float4*)(Ws + r * WS + q * 4) = v;
    }

    const int ntiles = (NTILES - bid + GRID - 1) / GRID;   // 2 or 3
    const int nch = ntiles * 8;
    const uint32_t asBase = smem_to_u32(As);

    // prologue: stages 0..RS-2
#pragma unroll
    for (int g = 0; g < RS - 1; g++) {
        issue_chunk(X, asBase, bid, g, tid);
        asm volatile("cp.async.commit_group;");
    }

    float acc[4][4][4];
#pragma unroll
    for (int mt = 0; mt < 4; mt++)
#pragma unroll
        for (int jn = 0; jn < 4; jn++)
#pragma unroll
            for (int v = 0; v < 4; v++) acc[mt][jn][v] = 0.f;

    const int aRowB = warpM * 64 + (lane >> 2);
    const int aColB = lane & 3;

    for (int g = 0; g < nch; g++) {
        if (g + RS - 1 < nch) issue_chunk(X, asBase, bid, g + RS - 1, tid);
        asm volatile("cp.async.commit_group;");   // one group per iter (maybe empty)
        asm volatile("cp.async.wait_group %0;" :: "n"(RS - 1));
        __syncthreads();

        const float* Ab = As + (g % RS) * ASTAGE;
        const int c = g & 7;
#pragma unroll
        for (int ks = 0; ks < 4; ks++) {
            int kloc = ks * 8 + aColB;
            uint32_t a[4][4];
#pragma unroll
            for (int mt = 0; mt < 4; mt++) {
                const float* p = Ab + (aRowB + mt * 16) * AS + kloc;
                a[mt][0] = __float_as_uint(p[0]);
                a[mt][1] = __float_as_uint(p[8 * AS]);
                a[mt][2] = __float_as_uint(p[4]);
                a[mt][3] = __float_as_uint(p[8 * AS + 4]);
            }
            int kg = c * 32 + ks * 8 + (lane & 3);
            uint32_t b[4][2];
#pragma unroll
            for (int jn = 0; jn < 4; jn++) {
                int d = warpN * 32 + jn * 8 + (lane >> 2);
                b[jn][0] = __float_as_uint(Ws[kg * WS + d]);
                b[jn][1] = __float_as_uint(Ws[(kg + 4) * WS + d]);
            }
#pragma unroll
            for (int mt = 0; mt < 4; mt++)
#pragma unroll
                for (int jn = 0; jn < 4; jn++)
                    mma_tf32(acc[mt][jn], a[mt], b[jn]);
        }

        if (c == 7) {
            // tile epilogue: + bm, store, reset acc
            int m0 = (bid + (g >> 3) * GRID) * 128;
#pragma unroll
            for (int jn = 0; jn < 4; jn++) {
                int col = warpN * 32 + jn * 8 + 2 * (lane & 3);
                float2 bm2;
                bm2.x = g_bm[col];
                bm2.y = g_bm[col + 1];
#pragma unroll
                for (int mt = 0; mt < 4; mt++) {
                    int row = m0 + warpM * 64 + mt * 16 + (lane >> 2);
                    if (row < NN) {
                        float2 o;
                        o.x = acc[mt][jn][0] + bm2.x;
                        o.y = acc[mt][jn][1] + bm2.y;
                        *(float2*)(out + (size_t)row * DD + col) = o;
                    }
                    if (row + 8 < NN) {
                        float2 o;
                        o.x = acc[mt][jn][2] + bm2.x;
                        o.y = acc[mt][jn][3] + bm2.y;
                        *(float2*)(out + (size_t)(row + 8) * DD + col) = o;
                    }
#pragma unroll
                    for (int v = 0; v < 4; v++) acc[mt][jn][v] = 0.f;
                }
            }
        }
        __syncthreads();   // protect stage (g%RS) before next-iter overwrite
    }
}

// ---------- launcher ----------
extern "C" void kernel_launch(void* const* d_in, const int* in_sizes, int n_in,
                              void* d_out, int out_size) {
    const float* xs = (const float*)d_in[1];   // source_input [N,256]
    const float* Wv = (const float*)d_in[6];
    const float* bv = (const float*)d_in[7];
    float* out = (float*)d_out;

    cudaFuncSetAttribute(vmean_gemm, cudaFuncAttributeMaxDynamicSharedMemorySize, VSMEM);

    prep_kernel<<<128, 256>>>(Wv, bv);
    vmean_gemm<<<GRID, 256, VSMEM>>>(xs, out);
}

// round 10
// speedup vs baseline: 91.6161x; 1.0942x over previous
#include <cuda_runtime.h>
#include <cstdint>

#define NN 50000
#define IC 256
#define DD 128
#define NH 8
#define HDIM 1024

#define NTILES ((NN + 127) / 128)    // 391
#define GRID 296                     // 2 persistent CTAs per SM

// Device scratch (allocation-free per harness rules)
__device__ float g_Wm[IC * DD];   // mean-over-heads V weight, tf32-rounded, [k][d]
__device__ float g_bm[DD];        // mean-over-heads V bias

__device__ __forceinline__ float to_tf32(float x) {
    float r; asm("cvt.rna.tf32.f32 %0, %1;" : "=f"(r) : "f"(x)); return r;
}
__device__ __forceinline__ uint32_t smem_to_u32(const void* p) {
    uint32_t a;
    asm("{ .reg .u64 t; cvta.to.shared.u64 t, %1; cvt.u32.u64 %0, t; }" : "=r"(a) : "l"(p));
    return a;
}

// mma.sync m16n8k8 tf32 (arch-agnostic PTX; HMMA on sm_103)
//  A: a0=(r,c) a1=(r+8,c) a2=(r,c+4) a3=(r+8,c+4), r=lane/4, c=lane%4
//  B: b0=(k=lane%4, n=lane/4) b1=(k+4, n)
//  D: d0=(r, 2c) d1=(r, 2c+1) d2=(r+8, 2c) d3=(r+8, 2c+1)
__device__ __forceinline__ void mma_tf32(float* d, const uint32_t* a, const uint32_t* b) {
    asm volatile(
        "mma.sync.aligned.m16n8k8.row.col.f32.tf32.tf32.f32 "
        "{%0,%1,%2,%3}, {%4,%5,%6,%7}, {%8,%9}, {%0,%1,%2,%3};"
        : "+f"(d[0]), "+f"(d[1]), "+f"(d[2]), "+f"(d[3])
        : "r"(a[0]), "r"(a[1]), "r"(a[2]), "r"(a[3]), "r"(b[0]), "r"(b[1]));
}

// ---------- prep: Wm[c][d] = tf32(mean_h Wv[c][h*128+d]); bm = mean_h bv ----------
__global__ void prep_kernel(const float* __restrict__ Wv, const float* __restrict__ bv) {
    int e = blockIdx.x * 256 + threadIdx.x;     // 0..32767
    int c = e >> 7, d = e & 127;
    float s = 0.f;
#pragma unroll
    for (int h = 0; h < NH; h++) s += Wv[(size_t)c * HDIM + h * DD + d];
    g_Wm[e] = to_tf32(s * 0.125f);
    if (e < DD) {
        float b = 0.f;
#pragma unroll
        for (int h = 0; h < NH; h++) b += bv[h * DD + e];
        g_bm[e] = b * 0.125f;
    }
}

// ---------- persistent GEMM: out[50000,128] = X[50000,256] @ Wm + bm ----------
// 296 persistent CTAs (2/SM). Both A (32-k chunk of the 128-row tile) and the
// matching W slice stream through one 3-stage cp.async ring. One __syncthreads
// per chunk. A/W fed to tf32 MMA unrounded (HW truncation; W pre-rounded).
#define AS 36
#define WSS 136
#define RS 3
#define ASTAGE (128 * AS)                 // floats
#define WSTAGE (32 * WSS)                 // floats
#define STAGE (ASTAGE + WSTAGE)           // 8960 floats = 35840 B
#define VSMEM (RS * STAGE * 4)            // 107520 B -> 2 CTAs/SM

__device__ __forceinline__ void issue_chunk(const float* __restrict__ X,
                                            uint32_t smBase, int bid, int g, int tid) {
    const int t = bid + (g >> 3) * GRID;   // tile index
    const int c = g & 7;                   // k-chunk within tile
    const int m0 = t * 128;
    const uint32_t st = smBase + (g % RS) * (STAGE * 4);
    // A: 128 rows x 32 k
#pragma unroll
    for (int i = 0; i < 4; i++) {
        int idx = tid + i * 256;           // 0..1023 float4 slots
        int r = idx >> 3, q = idx & 7;
        int gr = m0 + r;
        int grc = (gr < NN) ? gr : (NN - 1);
        const float* src = X + (size_t)grc * IC + c * 32 + q * 4;
        unsigned sz = (gr < NN) ? 16u : 0u;      // OOB rows zero-filled
        asm volatile("cp.async.cg.shared.global [%0], [%1], 16, %2;"
                     :: "r"(st + (r * AS + q * 4) * 4), "l"(src), "r"(sz));
    }
    // W: 32 k-rows x 128 d
#pragma unroll
    for (int i = 0; i < 4; i++) {
        int idx = tid + i * 256;           // 0..1023 float4 slots
        int r = idx >> 5, q = idx & 31;
        const float* src = g_Wm + (c * 32 + r) * DD + q * 4;
        asm volatile("cp.async.cg.shared.global [%0], [%1], 16;"
                     :: "r"(st + (ASTAGE + r * WSS + q * 4) * 4), "l"(src));
    }
}

__global__ __launch_bounds__(256, 2) void vmean_gemm(const float* __restrict__ X,
                                                     float* __restrict__ out) {
    extern __shared__ float sm[];
    const uint32_t smBase = smem_to_u32(sm);

    const int tid = threadIdx.x;
    const int lane = tid & 31;
    const int wid = tid >> 5;
    const int warpM = wid >> 2;      // 0..1  (64 rows)
    const int warpN = wid & 3;       // 0..3  (32 cols)
    const int bid = blockIdx.x;

    const int ntiles = (NTILES - bid + GRID - 1) / GRID;   // 2 (bid<95) or 1
    const int nch = ntiles * 8;

    // prologue: chunks 0..RS-2
#pragma unroll
    for (int g = 0; g < RS - 1; g++) {
        issue_chunk(X, smBase, bid, g, tid);
        asm volatile("cp.async.commit_group;");
    }
    asm volatile("cp.async.wait_group %0;" :: "n"(RS - 2));
    __syncthreads();

    float acc[4][4][4];
#pragma unroll
    for (int mt = 0; mt < 4; mt++)
#pragma unroll
        for (int jn = 0; jn < 4; jn++)
#pragma unroll
            for (int v = 0; v < 4; v++) acc[mt][jn][v] = 0.f;

    const int aRowB = warpM * 64 + (lane >> 2);
    const int aColB = lane & 3;
    const int bColB = warpN * 32 + (lane >> 2);

    for (int g = 0; g < nch; g++) {
        // ---- consume stage g%RS ----
        const float* Ab = sm + (g % RS) * STAGE;
        const float* Wb = Ab + ASTAGE;
#pragma unroll
        for (int ks = 0; ks < 4; ks++) {
            int kloc = ks * 8 + aColB;
            uint32_t a[4][4];
#pragma unroll
            for (int mt = 0; mt < 4; mt++) {
                const float* p = Ab + (aRowB + mt * 16) * AS + kloc;
                a[mt][0] = __float_as_uint(p[0]);
                a[mt][1] = __float_as_uint(p[8 * AS]);
                a[mt][2] = __float_as_uint(p[4]);
                a[mt][3] = __float_as_uint(p[8 * AS + 4]);
            }
            int kg = ks * 8 + (lane & 3);         // k local to chunk
            uint32_t b[4][2];
#pragma unroll
            for (int jn = 0; jn < 4; jn++) {
                int d = bColB + jn * 8;
                b[jn][0] = __float_as_uint(Wb[kg * WSS + d]);
                b[jn][1] = __float_as_uint(Wb[(kg + 4) * WSS + d]);
            }
#pragma unroll
            for (int mt = 0; mt < 4; mt++)
#pragma unroll
                for (int jn = 0; jn < 4; jn++)
                    mma_tf32(acc[mt][jn], a[mt], b[jn]);
        }

        if ((g & 7) == 7) {
            // tile epilogue: + bm, store, reset acc
            int m0 = (bid + (g >> 3) * GRID) * 128;
#pragma unroll
            for (int jn = 0; jn < 4; jn++) {
                int col = warpN * 32 + jn * 8 + 2 * (lane & 3);
                float2 bm2;
                bm2.x = g_bm[col];
                bm2.y = g_bm[col + 1];
#pragma unroll
                for (int mt = 0; mt < 4; mt++) {
                    int row = m0 + warpM * 64 + mt * 16 + (lane >> 2);
                    if (row < NN) {
                        float2 o;
                        o.x = acc[mt][jn][0] + bm2.x;
                        o.y = acc[mt][jn][1] + bm2.y;
                        *(float2*)(out + (size_t)row * DD + col) = o;
                    }
                    if (row + 8 < NN) {
                        float2 o;
                        o.x = acc[mt][jn][2] + bm2.x;
                        o.y = acc[mt][jn][3] + bm2.y;
                        *(float2*)(out + (size_t)(row + 8) * DD + col) = o;
                    }
#pragma unroll
                    for (int v = 0; v < 4; v++) acc[mt][jn][v] = 0.f;
                }
            }
        }

        // ---- refill: write stage (g+RS-1)%RS = (g-1)%RS, consumed last iter,
        // separated from its readers by the sync at end of iter g-1 ----
        if (g + RS - 1 < nch) issue_chunk(X, smBase, bid, g + RS - 1, tid);
        asm volatile("cp.async.commit_group;");          // one group per iter
        asm volatile("cp.async.wait_group %0;" :: "n"(RS - 2));
        __syncthreads();
    }
}

// ---------- launcher ----------
extern "C" void kernel_launch(void* const* d_in, const int* in_sizes, int n_in,
                              void* d_out, int out_size) {
    const float* xs = (const float*)d_in[1];   // source_input [N,256]
    const float* Wv = (const float*)d_in[6];
    const float* bv = (const float*)d_in[7];
    float* out = (float*)d_out;

    cudaFuncSetAttribute(vmean_gemm, cudaFuncAttributeMaxDynamicSharedMemorySize, VSMEM);

    prep_kernel<<<128, 256>>>(Wv, bv);
    vmean_gemm<<<GRID, 256, VSMEM>>>(xs, out);
}

// round 12
// speedup vs baseline: 94.7169x; 1.0338x over previous
#include <cuda_runtime.h>
#include <cstdint>

#define NN 50000
#define IC 256
#define DD 128
#define NH 8
#define HDIM 1024

#define TM 64                         // M tile
#define NTILES ((NN + TM - 1) / TM)   // 782

// Device scratch (allocation-free per harness rules)
__device__ float g_Wp[IC * DD];   // fragment-packed tf32 mean-V weight
__device__ float g_bm[DD];        // mean-over-heads V bias

__device__ __forceinline__ float to_tf32(float x) {
    float r; asm("cvt.rna.tf32.f32 %0, %1;" : "=f"(r) : "f"(x)); return r;
}
__device__ __forceinline__ uint32_t smem_to_u32(const void* p) {
    uint32_t a;
    asm("{ .reg .u64 t; cvta.to.shared.u64 t, %1; cvt.u32.u64 %0, t; }" : "=r"(a) : "l"(p));
    return a;
}

// mma.sync m16n8k8 tf32 (arch-agnostic PTX; HMMA on sm_103)
__device__ __forceinline__ void mma_tf32(float* d, const uint32_t* a, const uint32_t* b) {
    asm volatile(
        "mma.sync.aligned.m16n8k8.row.col.f32.tf32.tf32.f32 "
        "{%0,%1,%2,%3}, {%4,%5,%6,%7}, {%8,%9}, {%0,%1,%2,%3};"
        : "+f"(d[0]), "+f"(d[1]), "+f"(d[2]), "+f"(d[3])
        : "r"(a[0]), "r"(a[1]), "r"(a[2]), "r"(a[3]), "r"(b[0]), "r"(b[1]));
}

// ldmatrix x4: matrices = (rows0-7,k0-3),(rows8-15,k0-3),(rows0-7,k4-7),(rows8-15,k4-7)
__device__ __forceinline__ void ldsm_x4(uint32_t* a, uint32_t addr) {
    asm volatile("ldmatrix.sync.aligned.m8n8.x4.shared.b16 {%0,%1,%2,%3}, [%4];"
                 : "=r"(a[0]), "=r"(a[1]), "=r"(a[2]), "=r"(a[3]) : "r"(addr));
}

// ---------- prep: fragment-pack tf32(mean_h Wv), mean bias ----------
// element (k,d): chunk c=k/32, ks=(k/8)%4, s=(k/4)%2, lane=(d%8)*4+(k%4), nt=d/8
// g_Wp[c*4096 + ((nt*4+ks)*32 + lane)*2 + s]
__global__ void prep_kernel(const float* __restrict__ Wv, const float* __restrict__ bv) {
    int e = blockIdx.x * 256 + threadIdx.x;     // 0..32767
    int k = e >> 7, d = e & 127;
    float s = 0.f;
#pragma unroll
    for (int h = 0; h < NH; h++) s += Wv[(size_t)k * HDIM + h * DD + d];
    int c = k >> 5, ks = (k >> 3) & 3, sb = (k >> 2) & 1;
    int lane = ((d & 7) << 2) | (k & 3);
    int nt = d >> 3;
    g_Wp[c * 4096 + ((nt * 4 + ks) * 32 + lane) * 2 + sb] = to_tf32(s * 0.125f);
    if (e < DD) {
        float b = 0.f;
#pragma unroll
        for (int h = 0; h < NH; h++) b += bv[h * DD + e];
        g_bm[e] = b * 0.125f;
    }
}

// ---------- GEMM: out[50000,128] = X @ Wm + bm ----------
// 782 CTAs, tile 64x128, 8 warps 2(M)x4(N) -> warp 32x32. 4 CTAs/SM.
// RS=2 cp.async ring of (A 64x32-chunk, packed W 32x128-chunk).
#define AS 36
#define ASTAGE (TM * AS)              // 2304 floats
#define WSTAGE 4096                   // floats (packed chunk)
#define STAGE (ASTAGE + WSTAGE)       // 6400 floats = 25600 B
#define VSMEM (2 * STAGE * 4)         // 51200 B -> 4 CTAs/SM

__device__ __forceinline__ void issue_chunk(const float* __restrict__ X,
                                            uint32_t smBase, int m0, int c,
                                            int buf, int tid) {
    const uint32_t st = smBase + buf * (STAGE * 4);
    // A: 64 rows x 32 k
#pragma unroll
    for (int i = 0; i < 2; i++) {
        int idx = tid + i * 256;            // 0..511 float4 slots
        int r = idx >> 3, q = idx & 7;
        int gr = m0 + r;
        int grc = (gr < NN) ? gr : (NN - 1);
        const float* src = X + (size_t)grc * IC + c * 32 + q * 4;
        unsigned sz = (gr < NN) ? 16u : 0u;   // OOB rows zero-filled
        asm volatile("cp.async.cg.shared.global [%0], [%1], 16, %2;"
                     :: "r"(st + (r * AS + q * 4) * 4), "l"(src), "r"(sz));
    }
    // packed W chunk: 4096 floats contiguous
    const float* wsrc = g_Wp + c * 4096;
#pragma unroll
    for (int i = 0; i < 4; i++) {
        int idx = tid + i * 256;            // 0..1023 float4 slots
        asm volatile("cp.async.cg.shared.global [%0], [%1], 16;"
                     :: "r"(st + (ASTAGE + idx * 4) * 4), "l"(wsrc + idx * 4));
    }
}

__global__ __launch_bounds__(256, 4) void vmean_gemm(const float* __restrict__ X,
                                                     float* __restrict__ out) {
    extern __shared__ float sm[];
    const uint32_t smBase = smem_to_u32(sm);

    const int tid = threadIdx.x;
    const int lane = tid & 31;
    const int wid = tid >> 5;
    const int warpM = wid >> 2;      // 0..1 (32 rows each)
    const int warpN = wid & 3;       // 0..3 (32 cols each)
    const int m0 = blockIdx.x * TM;

    // ldmatrix lane-address offsets (bytes, relative to stage A base)
    const int rloc = lane & 15;
    const int col4 = (lane >> 4) << 2;
    uint32_t aRel[2];
#pragma unroll
    for (int mt = 0; mt < 2; mt++)
        aRel[mt] = ((warpM * 32 + mt * 16 + rloc) * AS + col4) * 4;

    // prologue
    issue_chunk(X, smBase, m0, 0, 0, tid);
    asm volatile("cp.async.commit_group;");
    issue_chunk(X, smBase, m0, 1, 1, tid);
    asm volatile("cp.async.commit_group;");

    float acc[2][4][4];
#pragma unroll
    for (int mt = 0; mt < 2; mt++)
#pragma unroll
        for (int jn = 0; jn < 4; jn++)
#pragma unroll
            for (int v = 0; v < 4; v++) acc[mt][jn][v] = 0.f;

    for (int g = 0; g < 8; g++) {
        const int buf = g & 1;
        asm volatile("cp.async.wait_group 1;");   // chunk g landed
        __syncthreads();

        const uint32_t stA = smBase + buf * (STAGE * 4);
        const float* Wb = sm + buf * STAGE + ASTAGE;
#pragma unroll
        for (int ks = 0; ks < 4; ks++) {
            uint32_t a[2][4];
#pragma unroll
            for (int mt = 0; mt < 2; mt++)
                ldsm_x4(a[mt], stA + aRel[mt] + ks * 32);
            uint32_t b[4][2];
#pragma unroll
            for (int jn = 0; jn < 4; jn++) {
                int nt = warpN * 4 + jn;
                float2 bb = *(const float2*)(Wb + ((nt * 4 + ks) * 32 + lane) * 2);
                b[jn][0] = __float_as_uint(bb.x);
                b[jn][1] = __float_as_uint(bb.y);
            }
#pragma unroll
            for (int mt = 0; mt < 2; mt++)
#pragma unroll
                for (int jn = 0; jn < 4; jn++)
                    mma_tf32(acc[mt][jn], a[mt], b[jn]);
        }
        __syncthreads();                          // readers done before refill
        if (g + 2 < 8) issue_chunk(X, smBase, m0, g + 2, buf, tid);
        asm volatile("cp.async.commit_group;");   // one group per iter
    }

    // epilogue: + bm, store
#pragma unroll
    for (int jn = 0; jn < 4; jn++) {
        int col = warpN * 32 + jn * 8 + 2 * (lane & 3);
        float2 bm2;
        bm2.x = g_bm[col];
        bm2.y = g_bm[col + 1];
#pragma unroll
        for (int mt = 0; mt < 2; mt++) {
            int row = m0 + warpM * 32 + mt * 16 + (lane >> 2);
            if (row < NN) {
                float2 o;
                o.x = acc[mt][jn][0] + bm2.x;
                o.y = acc[mt][jn][1] + bm2.y;
                *(float2*)(out + (size_t)row * DD + col) = o;
            }
            if (row + 8 < NN) {
                float2 o;
                o.x = acc[mt][jn][2] + bm2.x;
                o.y = acc[mt][jn][3] + bm2.y;
                *(float2*)(out + (size_t)(row + 8) * DD + col) = o;
            }
        }
    }
}

// ---------- launcher ----------
extern "C" void kernel_launch(void* const* d_in, const int* in_sizes, int n_in,
                              void* d_out, int out_size) {
    const float* xs = (const float*)d_in[1];   // source_input [N,256]
    const float* Wv = (const float*)d_in[6];
    const float* bv = (const float*)d_in[7];
    float* out = (float*)d_out;

    cudaFuncSetAttribute(vmean_gemm, cudaFuncAttributeMaxDynamicSharedMemorySize, VSMEM);

    prep_kernel<<<128, 256>>>(Wv, bv);
    vmean_gemm<<<NTILES, 256, VSMEM>>>(xs, out);
}

// round 14
// speedup vs baseline: 100.1616x; 1.0575x over previous
#include <cuda_runtime.h>
#include <cstdint>

#define NN 50000
#define IC 256
#define DD 128
#define NH 8
#define HDIM 1024

#define TM 64                         // M tile
#define NTILES ((NN + TM - 1) / TM)   // 782

// Device scratch (allocation-free per harness rules)
__device__ float g_Wp[IC * DD];   // fragment-packed tf32 mean-V weight
__device__ float g_bm[DD];        // mean-over-heads V bias

__device__ __forceinline__ float to_tf32(float x) {
    float r; asm("cvt.rna.tf32.f32 %0, %1;" : "=f"(r) : "f"(x)); return r;
}
__device__ __forceinline__ uint32_t smem_to_u32(const void* p) {
    uint32_t a;
    asm("{ .reg .u64 t; cvta.to.shared.u64 t, %1; cvt.u32.u64 %0, t; }" : "=r"(a) : "l"(p));
    return a;
}

// mma.sync m16n8k8 tf32 (arch-agnostic PTX; HMMA on sm_103)
__device__ __forceinline__ void mma_tf32(float* d, const uint32_t* a, const uint32_t* b) {
    asm volatile(
        "mma.sync.aligned.m16n8k8.row.col.f32.tf32.tf32.f32 "
        "{%0,%1,%2,%3}, {%4,%5,%6,%7}, {%8,%9}, {%0,%1,%2,%3};"
        : "+f"(d[0]), "+f"(d[1]), "+f"(d[2]), "+f"(d[3])
        : "r"(a[0]), "r"(a[1]), "r"(a[2]), "r"(a[3]), "r"(b[0]), "r"(b[1]));
}

// ldmatrix x4: matrices = (rows0-7,k0-3),(rows8-15,k0-3),(rows0-7,k4-7),(rows8-15,k4-7)
__device__ __forceinline__ void ldsm_x4(uint32_t* a, uint32_t addr) {
    asm volatile("ldmatrix.sync.aligned.m8n8.x4.shared.b16 {%0,%1,%2,%3}, [%4];"
                 : "=r"(a[0]), "=r"(a[1]), "=r"(a[2]), "=r"(a[3]) : "r"(addr));
}

// ---------- prep: fragment-pack tf32(mean_h Wv), mean bias ----------
// element (k,d): chunk c=k/32, ks=(k/8)%4, s=(k/4)%2, lane=(d%8)*4+(k%4), nt=d/8
// g_Wp[c*4096 + ((nt*4+ks)*32 + lane)*2 + s]
__global__ void prep_kernel(const float* __restrict__ Wv, const float* __restrict__ bv) {
    int e = blockIdx.x * 256 + threadIdx.x;     // 0..32767
    int k = e >> 7, d = e & 127;
    float s = 0.f;
#pragma unroll
    for (int h = 0; h < NH; h++) s += Wv[(size_t)k * HDIM + h * DD + d];
    int c = k >> 5, ks = (k >> 3) & 3, sb = (k >> 2) & 1;
    int lane = ((d & 7) << 2) | (k & 3);
    int nt = d >> 3;
    g_Wp[c * 4096 + ((nt * 4 + ks) * 32 + lane) * 2 + sb] = to_tf32(s * 0.125f);
    if (e < DD) {
        float b = 0.f;
#pragma unroll
        for (int h = 0; h < NH; h++) b += bv[h * DD + e];
        g_bm[e] = b * 0.125f;
    }
}

// ---------- GEMM: out[50000,128] = X @ Wm + bm ----------
// 782 CTAs, tile 64x128, 8 warps 2(M)x4(N) -> warp 32x32.
// A: 3-stage cp.async ring (9.2KB/stage), ONE syncthreads per chunk.
// B: LDG.64 straight from packed g_Wp (L2/L1 resident), reg-double-buffered.
#define AS 36
#define ASTAGE (TM * AS)              // 2304 floats = 9216 B
#define RS 3
#define VSMEM (RS * ASTAGE * 4)       // 27648 B

__device__ __forceinline__ void issue_chunk(const float* __restrict__ X,
                                            uint32_t smBase, int m0, int c, int tid) {
    const uint32_t st = smBase + (c % RS) * (ASTAGE * 4);
#pragma unroll
    for (int i = 0; i < 2; i++) {
        int idx = tid + i * 256;            // 0..511 float4 slots
        int r = idx >> 3, q = idx & 7;
        int gr = m0 + r;
        int grc = (gr < NN) ? gr : (NN - 1);
        const float* src = X + (size_t)grc * IC + c * 32 + q * 4;
        unsigned sz = (gr < NN) ? 16u : 0u;   // OOB rows zero-filled
        asm volatile("cp.async.cg.shared.global [%0], [%1], 16, %2;"
                     :: "r"(st + (r * AS + q * 4) * 4), "l"(src), "r"(sz));
    }
}

// load B fragments for one ks-step: 4 x LDG.64, coalesced (256B/warp)
__device__ __forceinline__ void load_b(uint32_t b[4][2], const float* __restrict__ Wc,
                                       int ks, int warpN, int lane) {
#pragma unroll
    for (int jn = 0; jn < 4; jn++) {
        int nt = warpN * 4 + jn;
        float2 bb = *(const float2*)(Wc + ((nt * 4 + ks) * 32 + lane) * 2);
        b[jn][0] = __float_as_uint(bb.x);
        b[jn][1] = __float_as_uint(bb.y);
    }
}

__global__ __launch_bounds__(256, 4) void vmean_gemm(const float* __restrict__ X,
                                                     float* __restrict__ out) {
    extern __shared__ float sm[];
    const uint32_t smBase = smem_to_u32(sm);

    const int tid = threadIdx.x;
    const int lane = tid & 31;
    const int wid = tid >> 5;
    const int warpM = wid >> 2;      // 0..1 (32 rows each)
    const int warpN = wid & 3;       // 0..3 (32 cols each)
    const int m0 = blockIdx.x * TM;

    // ldmatrix lane-address offsets (bytes, relative to stage base)
    const int rloc = lane & 15;
    const int col4 = (lane >> 4) << 2;
    uint32_t aRel[2];
#pragma unroll
    for (int mt = 0; mt < 2; mt++)
        aRel[mt] = ((warpM * 32 + mt * 16 + rloc) * AS + col4) * 4;

    // prologue: chunks 0,1
    issue_chunk(X, smBase, m0, 0, tid);
    asm volatile("cp.async.commit_group;");
    issue_chunk(X, smBase, m0, 1, tid);
    asm volatile("cp.async.commit_group;");

    float acc[2][4][4];
#pragma unroll
    for (int mt = 0; mt < 2; mt++)
#pragma unroll
        for (int jn = 0; jn < 4; jn++)
#pragma unroll
            for (int v = 0; v < 4; v++) acc[mt][jn][v] = 0.f;

    for (int g = 0; g < 8; g++) {
        asm volatile("cp.async.wait_group 1;");   // chunk g landed (this thread)
        __syncthreads();                          // publish to all warps

        // refill: buf (g+2)%RS == (g-1)%RS, consumed in iter g-1, protected
        // by the barrier above.
        if (g + 2 < 8) issue_chunk(X, smBase, m0, g + 2, tid);
        asm volatile("cp.async.commit_group;");   // one group per iter (maybe empty)

        const uint32_t stA = smBase + (g % RS) * (ASTAGE * 4);
        const float* Wc = g_Wp + (g & 7) * 4096;

        uint32_t bcur[4][2], bnxt[4][2];
        load_b(bcur, Wc, 0, warpN, lane);
#pragma unroll
        for (int ks = 0; ks < 4; ks++) {
            if (ks < 3) load_b(bnxt, Wc, ks + 1, warpN, lane);
            uint32_t a[2][4];
#pragma unroll
            for (int mt = 0; mt < 2; mt++)
                ldsm_x4(a[mt], stA + aRel[mt] + ks * 32);
#pragma unroll
            for (int mt = 0; mt < 2; mt++)
#pragma unroll
                for (int jn = 0; jn < 4; jn++)
                    mma_tf32(acc[mt][jn], a[mt], bcur[jn]);
#pragma unroll
            for (int jn = 0; jn < 4; jn++) {
                bcur[jn][0] = bnxt[jn][0];
                bcur[jn][1] = bnxt[jn][1];
            }
        }
    }

    // epilogue: + bm, store
#pragma unroll
    for (int jn = 0; jn < 4; jn++) {
        int col = warpN * 32 + jn * 8 + 2 * (lane & 3);
        float2 bm2;
        bm2.x = g_bm[col];
        bm2.y = g_bm[col + 1];
#pragma unroll
        for (int mt = 0; mt < 2; mt++) {
            int row = m0 + warpM * 32 + mt * 16 + (lane >> 2);
            if (row < NN) {
                float2 o;
                o.x = acc[mt][jn][0] + bm2.x;
                o.y = acc[mt][jn][1] + bm2.y;
                *(float2*)(out + (size_t)row * DD + col) = o;
            }
            if (row + 8 < NN) {
                float2 o;
                o.x = acc[mt][jn][2] + bm2.x;
                o.y = acc[mt][jn][3] + bm2.y;
                *(float2*)(out + (size_t)(row + 8) * DD + col) = o;
            }
        }
    }
}

// ---------- launcher ----------
extern "C" void kernel_launch(void* const* d_in, const int* in_sizes, int n_in,
                              void* d_out, int out_size) {
    const float* xs = (const float*)d_in[1];   // source_input [N,256]
    const float* Wv = (const float*)d_in[6];
    const float* bv = (const float*)d_in[7];
    float* out = (float*)d_out;

    cudaFuncSetAttribute(vmean_gemm, cudaFuncAttributeMaxDynamicSharedMemorySize, VSMEM);

    prep_kernel<<<128, 256>>>(Wv, bv);
    vmean_gemm<<<NTILES, 256, VSMEM>>>(xs, out);
}